// round 1
// baseline (speedup 1.0000x reference)
#include <cuda_runtime.h>
#include <math.h>

// ---------------- problem constants ----------------
#define T_  4
#define B_  8
#define N_  1024
#define C_  768
#define HD_ 3072
#define H_  8
#define D_  96
#define W_  8          // local attention window
#define NW_ (N_ / W_)  // 128 windows
#define M_  (T_ * B_ * N_)       // 32768 rows
#define MC_ (B_ * N_ * C_)       // per-timestep elems (C)   6291456
#define MH_ (B_ * N_ * HD_)      // per-timestep elems (Hd) 25165824

// ---------------- scratch (device globals; no allocation allowed) ----------------
__device__ float g_ybuf[(size_t)M_ * HD_];   // GEMM output scratch (max size)
__device__ float g_q  [(size_t)M_ * C_];
__device__ float g_k  [(size_t)M_ * C_];
__device__ float g_v  [(size_t)M_ * C_];
__device__ float g_o  [(size_t)M_ * C_];
__device__ float g_x2 [(size_t)M_ * C_];
__device__ float g_h  [(size_t)M_ * HD_];

// ---------------- GEMM: C[m,n] = (sum_k A[m,k]*W[n,k] + b[n]) * s[n] + t[n] ----------------
// A: (M,K) row-major, W: (N,K) row-major. M,N multiples of 128, K multiple of 16.
#define BM 128
#define BN 128
#define BK 16
#define TM 8
#define TN 8

__global__ __launch_bounds__(256) void gemm_bn_kernel(
    const float* __restrict__ A, const float* __restrict__ W,
    const float* __restrict__ bias, const float* __restrict__ bns,
    const float* __restrict__ bnt, float* __restrict__ C,
    int M, int N, int K)
{
    __shared__ float As[BK][BM];
    __shared__ float Bs[BK][BN];

    const int bcol = blockIdx.x;  // N tiles
    const int brow = blockIdx.y;  // M tiles
    const int tid  = threadIdx.x;

    const float* Ab = A + (size_t)brow * BM * K;
    const float* Wb = W + (size_t)bcol * BN * K;

    const int lrow = tid >> 2;          // 0..63
    const int lcol = (tid & 3) * 4;     // 0,4,8,12

    const int trow = (tid >> 4) * TM;   // 0..120
    const int tcol = (tid & 15) * TN;   // 0..120

    float acc[TM][TN];
#pragma unroll
    for (int i = 0; i < TM; i++)
#pragma unroll
        for (int j = 0; j < TN; j++) acc[i][j] = 0.f;

    for (int k0 = 0; k0 < K; k0 += BK) {
#pragma unroll
        for (int r = 0; r < 2; r++) {
            int row = lrow + r * 64;
            float4 va = *(const float4*)(Ab + (size_t)row * K + k0 + lcol);
            As[lcol + 0][row] = va.x;
            As[lcol + 1][row] = va.y;
            As[lcol + 2][row] = va.z;
            As[lcol + 3][row] = va.w;
            float4 vb = *(const float4*)(Wb + (size_t)row * K + k0 + lcol);
            Bs[lcol + 0][row] = vb.x;
            Bs[lcol + 1][row] = vb.y;
            Bs[lcol + 2][row] = vb.z;
            Bs[lcol + 3][row] = vb.w;
        }
        __syncthreads();

#pragma unroll
        for (int kk = 0; kk < BK; kk++) {
            float4 a0 = *(const float4*)&As[kk][trow];
            float4 a1 = *(const float4*)&As[kk][trow + 4];
            float4 b0 = *(const float4*)&Bs[kk][tcol];
            float4 b1 = *(const float4*)&Bs[kk][tcol + 4];
            float ar[TM] = {a0.x, a0.y, a0.z, a0.w, a1.x, a1.y, a1.z, a1.w};
            float br[TN] = {b0.x, b0.y, b0.z, b0.w, b1.x, b1.y, b1.z, b1.w};
#pragma unroll
            for (int i = 0; i < TM; i++)
#pragma unroll
                for (int j = 0; j < TN; j++) acc[i][j] += ar[i] * br[j];
        }
        __syncthreads();
    }

    // epilogue: (acc + b) * s + t
    float sreg[TN], breg[TN], treg[TN];
#pragma unroll
    for (int j = 0; j < TN; j++) {
        int n = bcol * BN + tcol + j;
        sreg[j] = bns[n];
        breg[j] = bias[n];
        treg[j] = bnt[n];
    }
#pragma unroll
    for (int i = 0; i < TM; i++) {
        size_t row = (size_t)(brow * BM + trow + i);
        float outv[TN];
#pragma unroll
        for (int j = 0; j < TN; j++)
            outv[j] = (acc[i][j] + breg[j]) * sreg[j] + treg[j];
        float4* dst = (float4*)(C + row * N + bcol * BN + tcol);
        dst[0] = make_float4(outv[0], outv[1], outv[2], outv[3]);
        dst[1] = make_float4(outv[4], outv[5], outv[6], outv[7]);
    }
}

// ---------------- LIF over T timesteps (tau=2, hard reset) ----------------
// in/out layout: (T, mc) with timestep stride mc.
__global__ void lif_kernel(const float* __restrict__ in, float* __restrict__ out,
                           float vth, int mc)
{
    int i = blockIdx.x * blockDim.x + threadIdx.x;
    if (i >= mc) return;
    float v = 0.f;
#pragma unroll
    for (int t = 0; t < T_; t++) {
        float x = in[(size_t)t * mc + i];
        v = v + (x - v) * 0.5f;
        float s = (v >= vth) ? 1.f : 0.f;
        out[(size_t)t * mc + i] = s;
        if (s > 0.f) v = 0.f;
    }
}

// out[t] = base[t] + lif(in)[t]
__global__ void lif_add_kernel(const float* __restrict__ in, const float* __restrict__ base,
                               float* __restrict__ out, float vth, int mc)
{
    int i = blockIdx.x * blockDim.x + threadIdx.x;
    if (i >= mc) return;
    float v = 0.f;
#pragma unroll
    for (int t = 0; t < T_; t++) {
        float x = in[(size_t)t * mc + i];
        v = v + (x - v) * 0.5f;
        float s = (v >= vth) ? 1.f : 0.f;
        out[(size_t)t * mc + i] = base[(size_t)t * mc + i] + s;
        if (s > 0.f) v = 0.f;
    }
}

// ---------------- local windowed attention ----------------
// q,k,v,o in (T,B,N,C) layout; head h occupies channels [h*D, (h+1)*D).
// grid: (NW_, H_, T_*B_), block: 128 threads.
__global__ __launch_bounds__(128) void attn_kernel(
    const float* __restrict__ q, const float* __restrict__ k,
    const float* __restrict__ v, float* __restrict__ o)
{
    const int wi = blockIdx.x;
    const int h  = blockIdx.y;
    const int tb = blockIdx.z;

    __shared__ float sq[W_ * D_];       // 8 x 96
    __shared__ float sk[2 * W_ * D_];   // 16 x 96
    __shared__ float sv[2 * W_ * D_];
    __shared__ float sp[W_ * 2 * W_];   // 8 x 16 attn

    const int tid = threadIdx.x;
    const size_t base = ((size_t)tb * N_) * C_ + (size_t)h * D_;

    for (int e = tid; e < W_ * D_; e += 128) {
        int i = e / D_, d = e % D_;
        sq[e] = q[base + (size_t)(wi * W_ + i) * C_ + d];
    }
    for (int e = tid; e < 2 * W_ * D_; e += 128) {
        int j = e / D_, d = e % D_;
        int n = wi * W_ + j - W_;   // j<8: previous window; j>=8: this window
        float kk = 0.f, vv = 0.f;
        if (n >= 0) {
            kk = k[base + (size_t)n * C_ + d];
            vv = v[base + (size_t)n * C_ + d];
        }
        sk[e] = kk;
        sv[e] = vv;
    }
    __syncthreads();

    // sim + softmax: one thread per (i,j) entry; 16-lane segmented reductions
    const int i = tid >> 4;
    const int j = tid & 15;
    const float scale = 0.10206207261596575f;  // 96^-0.5

    float dot = 0.f;
#pragma unroll
    for (int d = 0; d < D_; d++) dot += sq[i * D_ + d] * sk[j * D_ + d];
    float sim = dot * scale;
    if (wi == 0 && j < W_) sim = -INFINITY;

    float mx = sim;
#pragma unroll
    for (int off = 8; off; off >>= 1)
        mx = fmaxf(mx, __shfl_xor_sync(0xffffffffu, mx, off, 16));
    float p = __expf(0.f) * 0.f;  // placeholder avoided below
    p = expf(sim - mx);           // masked -> exp(-inf)=0
    float sum = p;
#pragma unroll
    for (int off = 8; off; off >>= 1)
        sum += __shfl_xor_sync(0xffffffffu, sum, off, 16);
    sp[i * 16 + j] = p / sum;
    __syncthreads();

    for (int e = tid; e < W_ * D_; e += 128) {
        int i2 = e / D_, d = e % D_;
        float accv = 0.f;
#pragma unroll
        for (int jj = 0; jj < 2 * W_; jj++) accv += sp[i2 * 16 + jj] * sv[jj * D_ + d];
        o[base + (size_t)(wi * W_ + i2) * C_ + d] = accv;
    }
}

// ---------------- host launcher ----------------
static void launch_gemm(const float* A, const float* W, const float* b,
                        const float* s, const float* t, float* C,
                        int M, int N, int K)
{
    dim3 grid(N / BN, M / BM);
    gemm_bn_kernel<<<grid, 256>>>(A, W, b, s, t, C, M, N, K);
}

extern "C" void kernel_launch(void* const* d_in, const int* in_sizes, int n_in,
                              void* d_out, int out_size)
{
    const float* x   = (const float*)d_in[0];
    const float* qw  = (const float*)d_in[1];
    const float* qb  = (const float*)d_in[2];
    const float* qs  = (const float*)d_in[3];
    const float* qt  = (const float*)d_in[4];
    const float* kw  = (const float*)d_in[5];
    const float* kb  = (const float*)d_in[6];
    const float* ks  = (const float*)d_in[7];
    const float* kt  = (const float*)d_in[8];
    const float* vw  = (const float*)d_in[9];
    const float* vb  = (const float*)d_in[10];
    const float* vs  = (const float*)d_in[11];
    const float* vt  = (const float*)d_in[12];
    const float* pw  = (const float*)d_in[13];
    const float* pb  = (const float*)d_in[14];
    const float* ps  = (const float*)d_in[15];
    const float* pt  = (const float*)d_in[16];
    const float* f1w = (const float*)d_in[17];
    const float* f1b = (const float*)d_in[18];
    const float* f1s = (const float*)d_in[19];
    const float* f1t = (const float*)d_in[20];
    const float* f2w = (const float*)d_in[21];
    const float* f2b = (const float*)d_in[22];
    const float* f2s = (const float*)d_in[23];
    const float* f2t = (const float*)d_in[24];
    float* out = (float*)d_out;

    float *ybuf, *bq, *bk, *bv, *bo, *bx2, *bh;
    cudaGetSymbolAddress((void**)&ybuf, g_ybuf);
    cudaGetSymbolAddress((void**)&bq,   g_q);
    cudaGetSymbolAddress((void**)&bk,   g_k);
    cudaGetSymbolAddress((void**)&bv,   g_v);
    cudaGetSymbolAddress((void**)&bo,   g_o);
    cudaGetSymbolAddress((void**)&bx2,  g_x2);
    cudaGetSymbolAddress((void**)&bh,   g_h);

    const int TH = 256;
    const int gC = (MC_ + TH - 1) / TH;
    const int gH = (MH_ + TH - 1) / TH;

    // Q, K, V branches
    launch_gemm(x, qw, qb, qs, qt, ybuf, M_, C_, C_);
    lif_kernel<<<gC, TH>>>(ybuf, bq, 1.0f, MC_);
    launch_gemm(x, kw, kb, ks, kt, ybuf, M_, C_, C_);
    lif_kernel<<<gC, TH>>>(ybuf, bk, 1.0f, MC_);
    launch_gemm(x, vw, vb, vs, vt, ybuf, M_, C_, C_);
    lif_kernel<<<gC, TH>>>(ybuf, bv, 1.0f, MC_);

    // local attention
    dim3 agrid(NW_, H_, T_ * B_);
    attn_kernel<<<agrid, 128>>>(bq, bk, bv, bo);

    // attn_lif (vth=0.5), in-place
    lif_kernel<<<gC, TH>>>(bo, bo, 0.5f, MC_);

    // proj + residual: x2 = x + lif(bn(proj(o)))
    launch_gemm(bo, pw, pb, ps, pt, ybuf, M_, C_, C_);
    lif_add_kernel<<<gC, TH>>>(ybuf, x, bx2, 1.0f, MC_);

    // MLP: h = lif(bn(f1(x2))); out = x2 + lif(bn(f2(h)))
    launch_gemm(bx2, f1w, f1b, f1s, f1t, ybuf, M_, HD_, C_);
    lif_kernel<<<gH, TH>>>(ybuf, bh, 1.0f, MH_);
    launch_gemm(bh, f2w, f2b, f2s, f2t, ybuf, M_, C_, HD_);
    lif_add_kernel<<<gC, TH>>>(ybuf, bx2, out, 1.0f, MC_);
}

// round 3
// speedup vs baseline: 2.0521x; 2.0521x over previous
#include <cuda_runtime.h>
#include <cuda_fp16.h>
#include <math.h>
#include <stdint.h>

// ---------------- problem constants ----------------
#define T_  4
#define B_  8
#define N_  1024
#define C_  768
#define HD_ 3072
#define H_  8
#define D_  96
#define W_  8
#define NW_ (N_ / W_)
#define M_  (T_ * B_ * N_)       // 32768
#define MC_ (B_ * N_ * C_)       // 6291456
#define MH_ (B_ * N_ * HD_)     // 25165824

// ---------------- scratch (device globals) ----------------
__device__ float  g_y   [(size_t)M_ * HD_];     // GEMM fp32 output scratch
__device__ __half g_xs  [(size_t)2 * M_ * C_];  // x splits hi/lo
__device__ __half g_x2s [(size_t)2 * M_ * C_];
__device__ __half g_sq  [(size_t)M_ * C_];
__device__ __half g_sk  [(size_t)M_ * C_];
__device__ __half g_sv  [(size_t)M_ * C_];
__device__ __half g_so  [(size_t)M_ * C_];
__device__ float  g_o   [(size_t)M_ * C_];
__device__ float  g_x2  [(size_t)M_ * C_];
__device__ __half g_h   [(size_t)M_ * HD_];
__device__ __half g_qws [(size_t)2 * C_ * C_];
__device__ __half g_kws [(size_t)2 * C_ * C_];
__device__ __half g_vws [(size_t)2 * C_ * C_];
__device__ __half g_pws [(size_t)2 * C_ * C_];
__device__ __half g_f1ws[(size_t)2 * HD_ * C_];
__device__ __half g_f2ws[(size_t)2 * C_ * HD_];

// ---------------- helpers ----------------
__device__ __forceinline__ uint32_t smem_u32(const void* p) {
    uint32_t a;
    asm("{ .reg .u64 t; cvta.to.shared.u64 t, %1; cvt.u32.u64 %0, t; }" : "=r"(a) : "l"(p));
    return a;
}
__device__ __forceinline__ void cp16(uint32_t dst, const void* src) {
    asm volatile("cp.async.cg.shared.global [%0], [%1], 16;" :: "r"(dst), "l"(src) : "memory");
}
#define CP_COMMIT() asm volatile("cp.async.commit_group;" ::: "memory")
#define CP_WAIT1()  asm volatile("cp.async.wait_group 1;" ::: "memory")

__device__ __forceinline__ void ldm4(uint32_t* r, uint32_t addr) {
    asm volatile("ldmatrix.sync.aligned.m8n8.x4.shared.b16 {%0,%1,%2,%3}, [%4];"
        : "=r"(r[0]), "=r"(r[1]), "=r"(r[2]), "=r"(r[3]) : "r"(addr));
}
__device__ __forceinline__ void mma16816(float* c, const uint32_t* a, const uint32_t* b) {
    asm volatile("mma.sync.aligned.m16n8k16.row.col.f32.f16.f16.f32 "
        "{%0,%1,%2,%3}, {%4,%5,%6,%7}, {%8,%9}, {%0,%1,%2,%3};"
        : "+f"(c[0]), "+f"(c[1]), "+f"(c[2]), "+f"(c[3])
        : "r"(a[0]), "r"(a[1]), "r"(a[2]), "r"(a[3]), "r"(b[0]), "r"(b[1]));
}

// smem layout: padded rows of 80B (32 fp16 + 16B pad) -> conflict-free ldmatrix
#define AH_OFF 0
#define AL_OFF 10240
#define BH_OFF 20480
#define BL_OFF 30720
#define STAGE  40960
#define BIAS_OFF (2 * STAGE)            // 81920
#define GSMEM (BIAS_OFF + 3 * 128 * 4)  // 83456

// ---------------- fp16 split-emulated GEMM ----------------
// out[m,n] = (acc_hh + 2^-11*(acc_hl+lh) + bias[n]) * s[n] + t[n]
// A: (M,K) hi/lo, B = W: (N,K) hi/lo (lo pre-scaled by 2048). binary: A exact fp16, skip Al.
__global__ __launch_bounds__(512) void gemm_h_kernel(
    const __half* __restrict__ Ah, const __half* __restrict__ Al,
    const __half* __restrict__ Bh, const __half* __restrict__ Bl,
    const float* __restrict__ bias, const float* __restrict__ bns,
    const float* __restrict__ bnt, float* __restrict__ out,
    int N, int K, int binary)
{
    extern __shared__ char sm[];
    const int tid = threadIdx.x, wid = tid >> 5, lane = tid & 31;
    const int bcol = blockIdx.x, brow = blockIdx.y;
    const int wm = wid & 3, wn = wid >> 2;   // 4x4 warp grid, warp tile 32x32
    const uint32_t sb = smem_u32(sm);

    float* sbias = (float*)(sm + BIAS_OFF);
    float* sscl  = sbias + 128;
    float* ssht  = sbias + 256;
    if (tid < 128) {
        int n = bcol * 128 + tid;
        sbias[tid] = bias[n]; sscl[tid] = bns[n]; ssht[tid] = bnt[n];
    }

    const int lr = tid >> 2, lc = tid & 3;   // loader: row 0..127, chunk 0..3
    const size_t aoff = (size_t)(brow * 128 + lr) * K + lc * 8;
    const size_t boff = (size_t)(bcol * 128 + lr) * K + lc * 8;
    const uint32_t sdst = lr * 80 + lc * 16;

    auto load = [&](int buf, int chunk) {
        const uint32_t st = sb + buf * STAGE;
        const int k0 = chunk * 32;
        cp16(st + AH_OFF + sdst, Ah + aoff + k0);
        if (!binary) cp16(st + AL_OFF + sdst, Al + aoff + k0);
        cp16(st + BH_OFF + sdst, Bh + boff + k0);
        cp16(st + BL_OFF + sdst, Bl + boff + k0);
        CP_COMMIT();
    };

    float acc0[2][4][4] = {};
    float acc1[2][4][4] = {};

    load(0, 0);
    load(1, 1);
    const int nch = K >> 5;

    const int lrow  = (lane & 7) + ((lane >> 3) & 1) * 8;
    const int lhalf = lane >> 4;

    for (int i = 0; i < nch; i++) {
        CP_WAIT1();
        __syncthreads();
        const uint32_t st = sb + (i & 1) * STAGE;
#pragma unroll
        for (int ks = 0; ks < 2; ks++) {
            const uint32_t choff = (uint32_t)(ks * 2 + lhalf) * 16;
            uint32_t ah[2][4], al[2][4], bh[4][2], bl[4][2];
#pragma unroll
            for (int mt = 0; mt < 2; mt++) {
                uint32_t ra = st + AH_OFF + (uint32_t)(wm * 32 + mt * 16 + lrow) * 80 + choff;
                ldm4(ah[mt], ra);
                if (!binary) ldm4(al[mt], ra + (AL_OFF - AH_OFF));
            }
#pragma unroll
            for (int g = 0; g < 2; g++) {
                uint32_t rb = st + BH_OFF + (uint32_t)(wn * 32 + g * 16 + lrow) * 80 + choff;
                uint32_t t4[4];
                ldm4(t4, rb);
                bh[g * 2][0] = t4[0]; bh[g * 2][1] = t4[2];
                bh[g * 2 + 1][0] = t4[1]; bh[g * 2 + 1][1] = t4[3];
                ldm4(t4, rb + (BL_OFF - BH_OFF));
                bl[g * 2][0] = t4[0]; bl[g * 2][1] = t4[2];
                bl[g * 2 + 1][0] = t4[1]; bl[g * 2 + 1][1] = t4[3];
            }
#pragma unroll
            for (int mt = 0; mt < 2; mt++)
#pragma unroll
                for (int nt = 0; nt < 4; nt++) {
                    mma16816(acc0[mt][nt], ah[mt], bh[nt]);
                    mma16816(acc1[mt][nt], ah[mt], bl[nt]);
                    if (!binary) mma16816(acc1[mt][nt], al[mt], bh[nt]);
                }
        }
        __syncthreads();
        if (i + 2 < nch) load(i & 1, i + 2);
        else CP_COMMIT();
    }

    // epilogue
    const float LS = 4.8828125e-4f;  // 2^-11
    const int gr = lane >> 2, gc = (lane & 3) * 2;
#pragma unroll
    for (int mt = 0; mt < 2; mt++)
#pragma unroll
        for (int nt = 0; nt < 4; nt++) {
            const int cc = wn * 32 + nt * 8 + gc;
            const int row0 = brow * 128 + wm * 32 + mt * 16 + gr;
            const float b0 = sbias[cc], b1 = sbias[cc + 1];
            const float s0 = sscl[cc],  s1 = sscl[cc + 1];
            const float t0 = ssht[cc],  t1 = ssht[cc + 1];
            float* o0 = out + (size_t)row0 * N + bcol * 128 + cc;
            float* o1 = out + (size_t)(row0 + 8) * N + bcol * 128 + cc;
            float v00 = (acc0[mt][nt][0] + LS * acc1[mt][nt][0] + b0) * s0 + t0;
            float v01 = (acc0[mt][nt][1] + LS * acc1[mt][nt][1] + b1) * s1 + t1;
            float v10 = (acc0[mt][nt][2] + LS * acc1[mt][nt][2] + b0) * s0 + t0;
            float v11 = (acc0[mt][nt][3] + LS * acc1[mt][nt][3] + b1) * s1 + t1;
            *(float2*)o0 = make_float2(v00, v01);
            *(float2*)o1 = make_float2(v10, v11);
        }
}

// ---------------- split fp32 -> fp16 hi + scaled lo ----------------
__global__ void split2_kernel(const float* __restrict__ in, __half* __restrict__ hi,
                              __half* __restrict__ lo, size_t n4)
{
    size_t i = (size_t)blockIdx.x * blockDim.x + threadIdx.x;
    if (i >= n4) return;
    float4 v = ((const float4*)in)[i];
    float xs[4] = {v.x, v.y, v.z, v.w};
    __half h[4], l[4];
#pragma unroll
    for (int q = 0; q < 4; q++) {
        float x = xs[q];
        __half hh = __float2half_rn(x);
        float r = (x - __half2float(hh)) * 2048.0f;
        h[q] = hh;
        l[q] = __float2half_rn(r);
    }
    ((__half2*)hi)[i * 2 + 0] = __halves2half2(h[0], h[1]);
    ((__half2*)hi)[i * 2 + 1] = __halves2half2(h[2], h[3]);
    ((__half2*)lo)[i * 2 + 0] = __halves2half2(l[0], l[1]);
    ((__half2*)lo)[i * 2 + 1] = __halves2half2(l[2], l[3]);
}

// ---------------- LIF variants ----------------
__global__ void lif_spike_h(const float* __restrict__ in, __half* __restrict__ out,
                            float vth, int mc)
{
    int i = blockIdx.x * blockDim.x + threadIdx.x;
    if (i >= mc) return;
    float v = 0.f;
#pragma unroll
    for (int t = 0; t < T_; t++) {
        float x = in[(size_t)t * mc + i];
        v = v + (x - v) * 0.5f;
        float s = (v >= vth) ? 1.f : 0.f;
        out[(size_t)t * mc + i] = __float2half(s);
        if (s > 0.f) v = 0.f;
    }
}

__global__ void lif_add_kernel(const float* __restrict__ in, const float* __restrict__ base,
                               float* __restrict__ out, float vth, int mc)
{
    int i = blockIdx.x * blockDim.x + threadIdx.x;
    if (i >= mc) return;
    float v = 0.f;
#pragma unroll
    for (int t = 0; t < T_; t++) {
        float x = in[(size_t)t * mc + i];
        v = v + (x - v) * 0.5f;
        float s = (v >= vth) ? 1.f : 0.f;
        out[(size_t)t * mc + i] = base[(size_t)t * mc + i] + s;
        if (s > 0.f) v = 0.f;
    }
}

// ---------------- local windowed attention (fp16 spike inputs) ----------------
__global__ __launch_bounds__(128) void attn_kernel(
    const __half* __restrict__ q, const __half* __restrict__ k,
    const __half* __restrict__ v, float* __restrict__ o)
{
    const int wi = blockIdx.x;
    const int h  = blockIdx.y;
    const int tb = blockIdx.z;

    __shared__ float sq[W_ * D_];
    __shared__ float sk[2 * W_ * D_];
    __shared__ float sv[2 * W_ * D_];
    __shared__ float sp[W_ * 2 * W_];

    const int tid = threadIdx.x;
    const size_t base = ((size_t)tb * N_) * C_ + (size_t)h * D_;

    for (int e = tid; e < W_ * D_; e += 128) {
        int i = e / D_, d = e % D_;
        sq[e] = __half2float(q[base + (size_t)(wi * W_ + i) * C_ + d]);
    }
    for (int e = tid; e < 2 * W_ * D_; e += 128) {
        int j = e / D_, d = e % D_;
        int n = wi * W_ + j - W_;
        float kk = 0.f, vv = 0.f;
        if (n >= 0) {
            kk = __half2float(k[base + (size_t)n * C_ + d]);
            vv = __half2float(v[base + (size_t)n * C_ + d]);
        }
        sk[e] = kk;
        sv[e] = vv;
    }
    __syncthreads();

    const int i = tid >> 4;
    const int j = tid & 15;
    const float scale = 0.10206207261596575f;  // 96^-0.5

    float dot = 0.f;
#pragma unroll
    for (int d = 0; d < D_; d++) dot += sq[i * D_ + d] * sk[j * D_ + d];
    float sim = dot * scale;
    if (wi == 0 && j < W_) sim = -INFINITY;

    float mx = sim;
#pragma unroll
    for (int off = 8; off; off >>= 1)
        mx = fmaxf(mx, __shfl_xor_sync(0xffffffffu, mx, off, 16));
    float p = expf(sim - mx);
    float sum = p;
#pragma unroll
    for (int off = 8; off; off >>= 1)
        sum += __shfl_xor_sync(0xffffffffu, sum, off, 16);
    sp[i * 16 + j] = p / sum;
    __syncthreads();

    for (int e = tid; e < W_ * D_; e += 128) {
        int i2 = e / D_, d = e % D_;
        float accv = 0.f;
#pragma unroll
        for (int jj = 0; jj < 2 * W_; jj++) accv += sp[i2 * 16 + jj] * sv[jj * D_ + d];
        o[base + (size_t)(wi * W_ + i2) * C_ + d] = accv;
    }
}

// ---------------- host ----------------
static void launch_gemm(const __half* ah, const __half* al, const __half* ws,
                        size_t wlen, const float* b, const float* s, const float* t,
                        float* out, int N, int K, int binary)
{
    dim3 grid(N / 128, M_ / 128);
    gemm_h_kernel<<<grid, 512, GSMEM>>>(ah, al, ws, ws + wlen, b, s, t, out, N, K, binary);
}

extern "C" void kernel_launch(void* const* d_in, const int* in_sizes, int n_in,
                              void* d_out, int out_size)
{
    const float* x   = (const float*)d_in[0];
    const float* qw  = (const float*)d_in[1];
    const float* qb  = (const float*)d_in[2];
    const float* qs  = (const float*)d_in[3];
    const float* qt  = (const float*)d_in[4];
    const float* kw  = (const float*)d_in[5];
    const float* kb  = (const float*)d_in[6];
    const float* ks  = (const float*)d_in[7];
    const float* kt  = (const float*)d_in[8];
    const float* vw  = (const float*)d_in[9];
    const float* vb  = (const float*)d_in[10];
    const float* vs  = (const float*)d_in[11];
    const float* vt  = (const float*)d_in[12];
    const float* pw  = (const float*)d_in[13];
    const float* pb  = (const float*)d_in[14];
    const float* ps  = (const float*)d_in[15];
    const float* pt  = (const float*)d_in[16];
    const float* f1w = (const float*)d_in[17];
    const float* f1b = (const float*)d_in[18];
    const float* f1s = (const float*)d_in[19];
    const float* f1t = (const float*)d_in[20];
    const float* f2w = (const float*)d_in[21];
    const float* f2b = (const float*)d_in[22];
    const float* f2s = (const float*)d_in[23];
    const float* f2t = (const float*)d_in[24];
    float* out = (float*)d_out;

    float *y, *o, *x2;
    __half *xs, *x2s, *sq, *sk, *sv, *so, *hh;
    __half *qws, *kws, *vws, *pws, *f1ws, *f2ws;
    cudaGetSymbolAddress((void**)&y,   g_y);
    cudaGetSymbolAddress((void**)&o,   g_o);
    cudaGetSymbolAddress((void**)&x2,  g_x2);
    cudaGetSymbolAddress((void**)&xs,  g_xs);
    cudaGetSymbolAddress((void**)&x2s, g_x2s);
    cudaGetSymbolAddress((void**)&sq,  g_sq);
    cudaGetSymbolAddress((void**)&sk,  g_sk);
    cudaGetSymbolAddress((void**)&sv,  g_sv);
    cudaGetSymbolAddress((void**)&so,  g_so);
    cudaGetSymbolAddress((void**)&hh,  g_h);
    cudaGetSymbolAddress((void**)&qws, g_qws);
    cudaGetSymbolAddress((void**)&kws, g_kws);
    cudaGetSymbolAddress((void**)&vws, g_vws);
    cudaGetSymbolAddress((void**)&pws, g_pws);
    cudaGetSymbolAddress((void**)&f1ws, g_f1ws);
    cudaGetSymbolAddress((void**)&f2ws, g_f2ws);

    cudaFuncSetAttribute(gemm_h_kernel, cudaFuncAttributeMaxDynamicSharedMemorySize, GSMEM);

    const int TH = 256;
    const int gC = (MC_ + TH - 1) / TH;
    const int gH = (MH_ + TH - 1) / TH;
    const size_t LWC = (size_t)C_ * C_;
    const size_t LW1 = (size_t)HD_ * C_;
    const size_t LXC = (size_t)M_ * C_;

    // weight splits (hi + 2048*residual)
    split2_kernel<<<(int)(LWC / 1024), TH>>>(qw, qws, qws + LWC, LWC / 4);
    split2_kernel<<<(int)(LWC / 1024), TH>>>(kw, kws, kws + LWC, LWC / 4);
    split2_kernel<<<(int)(LWC / 1024), TH>>>(vw, vws, vws + LWC, LWC / 4);
    split2_kernel<<<(int)(LWC / 1024), TH>>>(pw, pws, pws + LWC, LWC / 4);
    split2_kernel<<<(int)(LW1 / 1024), TH>>>(f1w, f1ws, f1ws + LW1, LW1 / 4);
    split2_kernel<<<(int)(LW1 / 1024), TH>>>(f2w, f2ws, f2ws + LW1, LW1 / 4);

    // x splits
    split2_kernel<<<(int)(LXC / 1024), TH>>>(x, xs, xs + LXC, LXC / 4);

    // Q, K, V: emulated-fp32 GEMM + BN, then LIF -> fp16 spikes
    launch_gemm(xs, xs + LXC, qws, LWC, qb, qs, qt, y, C_, C_, 0);
    lif_spike_h<<<gC, TH>>>(y, sq, 1.0f, MC_);
    launch_gemm(xs, xs + LXC, kws, LWC, kb, ks, kt, y, C_, C_, 0);
    lif_spike_h<<<gC, TH>>>(y, sk, 1.0f, MC_);
    launch_gemm(xs, xs + LXC, vws, LWC, vb, vs, vt, y, C_, C_, 0);
    lif_spike_h<<<gC, TH>>>(y, sv, 1.0f, MC_);

    // local attention + attn-LIF (vth=0.5)
    dim3 agrid(NW_, H_, T_ * B_);
    attn_kernel<<<agrid, 128>>>(sq, sk, sv, o);
    lif_spike_h<<<gC, TH>>>(o, so, 0.5f, MC_);

    // proj (binary A) + residual: x2 = x + lif(bn(proj(so)))
    launch_gemm(so, nullptr, pws, LWC, pb, ps, pt, y, C_, C_, 1);
    lif_add_kernel<<<gC, TH>>>(y, x, x2, 1.0f, MC_);

    // MLP
    split2_kernel<<<(int)(LXC / 1024), TH>>>(x2, x2s, x2s + LXC, LXC / 4);
    launch_gemm(x2s, x2s + LXC, f1ws, LW1, f1b, f1s, f1t, y, HD_, C_, 0);
    lif_spike_h<<<gH, TH>>>(y, hh, 1.0f, MH_);
    launch_gemm(hh, nullptr, f2ws, LW1, f2b, f2s, f2t, y, C_, HD_, 1);
    lif_add_kernel<<<gC, TH>>>(y, x2, out, 1.0f, MC_);
}